// round 6
// baseline (speedup 1.0000x reference)
#include <cuda_runtime.h>
#include <cuda_bf16.h>
#include <mma.h>
#include <cstdint>

using namespace nvcuda;
typedef __nv_bfloat16 bf16;

#define Bsz 8192
#define Tn  12
#define DIN 64
#define HID 512
#define ENCD 128
#define Rr  64

// ================= device-global scratch =================
__device__ __align__(256) bf16  g_ench[Tn * Bsz * ENCD];   // [t][b][e] hi
__device__ __align__(256) bf16  g_encl[Tn * Bsz * ENCD];   // lo
__device__ __align__(256) float g_v[2][Bsz * Rr];
__device__ __align__(256) bf16  g_W1hi[HID * DIN],  g_W1lo[HID * DIN];
__device__ __align__(256) bf16  g_W2hi[ENCD * HID], g_W2lo[ENCD * HID];
// H_mid as GEMM-B: [t][e][n = r*64+p]
__device__ __align__(256) bf16  g_HBh[(Tn - 2) * ENCD * Rr * Rr];
__device__ __align__(256) bf16  g_HBl[(Tn - 2) * ENCD * Rr * Rr];

__device__ __forceinline__ uint32_t smem_u32(const void* p) {
    uint32_t a;
    asm("{ .reg .u64 t; cvta.to.shared.u64 t, %1; cvt.u32.u64 %0, t; }" : "=r"(a) : "l"(p));
    return a;
}
__device__ __forceinline__ void cp16(uint32_t dst, const void* src) {
    asm volatile("cp.async.cg.shared.global [%0], [%1], 16;" :: "r"(dst), "l"(src));
}
#define CP_COMMIT()  asm volatile("cp.async.commit_group;")
#define CP_WAIT(N)   asm volatile("cp.async.wait_group %0;" :: "n"(N))

// ================= prep: W splits =================
__global__ void prep_w_kernel(const float* __restrict__ W1,
                              const float* __restrict__ W2) {
    const int n1 = HID * DIN, n2 = ENCD * HID;
    for (int i = blockIdx.x * blockDim.x + threadIdx.x; i < n1 + n2;
         i += gridDim.x * blockDim.x) {
        const float* s; bf16 *h, *l; int j;
        if (i < n1) { s = W1; h = g_W1hi; l = g_W1lo; j = i; }
        else        { s = W2; h = g_W2hi; l = g_W2lo; j = i - n1; }
        float v = s[j];
        bf16 hi = __float2bfloat16(v);
        h[j] = hi;
        l[j] = __float2bfloat16(v - __bfloat162float(hi));
    }
}

// ================= prep: Hm[t,p,e,r] -> HB[t][e][r*64+p] hi/lo =================
__global__ __launch_bounds__(256) void prep_hb_kernel(const float* __restrict__ Hm) {
    __shared__ float tile[64][65];              // [p][r]
    const int t = blockIdx.x >> 7;
    const int e = blockIdx.x & 127;
    const int tid = threadIdx.x;
    for (int i = tid; i < 64 * 64; i += 256) {
        int p = i >> 6, r = i & 63;
        tile[p][r] = Hm[(((size_t)(t * 64 + p) * 128) + e) * 64 + r];
    }
    __syncthreads();
    bf16* dh = g_HBh + (size_t)(t * 128 + e) * 4096;
    bf16* dl = g_HBl + (size_t)(t * 128 + e) * 4096;
    for (int c = tid; c < 4096; c += 256) {
        int r = c >> 6, p = c & 63;
        float v = tile[p][r];
        bf16 hi = __float2bfloat16(v);
        dh[c] = hi;
        dl[c] = __float2bfloat16(v - __bfloat162float(hi));
    }
}

// ================= encoder v2 (unchanged from R5) =================
#define EX_H 0u
#define EX_L (EX_H + 64u * 72u * 2u)
#define EH_H (EX_L + 64u * 72u * 2u)
#define EH_L (EH_H + 64u * 520u * 2u)
#define E_ST (EH_L + 64u * 520u * 2u)
#define ENC2_SMEM (E_ST + 8u * 320u * 4u)

__global__ __launch_bounds__(256, 1) void encoder2_kernel(const float* __restrict__ x,
                                                          const float* __restrict__ b1,
                                                          const float* __restrict__ b2) {
    extern __shared__ char smem[];
    bf16* xs_hi = (bf16*)(smem + EX_H);
    bf16* xs_lo = (bf16*)(smem + EX_L);
    bf16* hs_hi = (bf16*)(smem + EH_H);
    bf16* hs_lo = (bf16*)(smem + EH_L);
    float* stg_base = (float*)(smem + E_ST);

    const int tid = threadIdx.x, w = tid >> 5, lane = tid & 31;
    const int wy = w >> 2, wx = w & 3;
    const int n0 = blockIdx.x * 64;
    float* stg = stg_base + w * 320;
    const int frow = lane >> 1, fcol = (lane & 1) * 8;

    #pragma unroll
    for (int k = 0; k < 16; k++) {
        int idx = tid + k * 256;
        int r = idx >> 6, c = idx & 63;
        float v = x[(size_t)(n0 + r) * DIN + c];
        bf16 hi = __float2bfloat16(v);
        xs_hi[r * 72 + c] = hi;
        xs_lo[r * 72 + c] = __float2bfloat16(v - __bfloat162float(hi));
    }
    __syncthreads();

    #pragma unroll
    for (int pass = 0; pass < 2; pass++) {
        const int cb = wx * 128 + pass * 64;
        wmma::fragment<wmma::accumulator, 16, 16, 16, float> acc[2][4];
        #pragma unroll
        for (int rf = 0; rf < 2; rf++)
            #pragma unroll
            for (int j = 0; j < 4; j++) wmma::fill_fragment(acc[rf][j], 0.0f);
        #pragma unroll
        for (int kk = 0; kk < 4; kk++) {
            wmma::fragment<wmma::matrix_a, 16, 16, 16, bf16, wmma::row_major> ahi[2], alo[2];
            #pragma unroll
            for (int rf = 0; rf < 2; rf++) {
                wmma::load_matrix_sync(ahi[rf], xs_hi + (wy * 32 + rf * 16) * 72 + kk * 16, 72);
                wmma::load_matrix_sync(alo[rf], xs_lo + (wy * 32 + rf * 16) * 72 + kk * 16, 72);
            }
            #pragma unroll
            for (int j = 0; j < 4; j++) {
                wmma::fragment<wmma::matrix_b, 16, 16, 16, bf16, wmma::col_major> bhi, blo;
                wmma::load_matrix_sync(bhi, g_W1hi + (cb + j * 16) * DIN + kk * 16, DIN);
                wmma::load_matrix_sync(blo, g_W1lo + (cb + j * 16) * DIN + kk * 16, DIN);
                #pragma unroll
                for (int rf = 0; rf < 2; rf++) {
                    wmma::mma_sync(acc[rf][j], ahi[rf], bhi, acc[rf][j]);
                    wmma::mma_sync(acc[rf][j], alo[rf], bhi, acc[rf][j]);
                    wmma::mma_sync(acc[rf][j], ahi[rf], blo, acc[rf][j]);
                }
            }
        }
        #pragma unroll
        for (int rf = 0; rf < 2; rf++)
            #pragma unroll
            for (int j = 0; j < 4; j++) {
                wmma::store_matrix_sync(stg, acc[rf][j], 20, wmma::mem_row_major);
                __syncwarp();
                const int rbase = wy * 32 + rf * 16 + frow;
                #pragma unroll
                for (int cc = 0; cc < 8; cc++) {
                    int gc = cb + j * 16 + fcol + cc;
                    float v = fmaxf(stg[frow * 20 + fcol + cc] + b1[gc], 0.0f);
                    bf16 hi = __float2bfloat16(v);
                    hs_hi[rbase * 520 + gc] = hi;
                    hs_lo[rbase * 520 + gc] = __float2bfloat16(v - __bfloat162float(hi));
                }
                __syncwarp();
            }
    }
    __syncthreads();

    {
        wmma::fragment<wmma::accumulator, 16, 16, 16, float> acc[2][2];
        #pragma unroll
        for (int rf = 0; rf < 2; rf++)
            #pragma unroll
            for (int j = 0; j < 2; j++) wmma::fill_fragment(acc[rf][j], 0.0f);
        #pragma unroll 8
        for (int kk = 0; kk < 32; kk++) {
            wmma::fragment<wmma::matrix_a, 16, 16, 16, bf16, wmma::row_major> ahi[2], alo[2];
            #pragma unroll
            for (int rf = 0; rf < 2; rf++) {
                wmma::load_matrix_sync(ahi[rf], hs_hi + (wy * 32 + rf * 16) * 520 + kk * 16, 520);
                wmma::load_matrix_sync(alo[rf], hs_lo + (wy * 32 + rf * 16) * 520 + kk * 16, 520);
            }
            #pragma unroll
            for (int j = 0; j < 2; j++) {
                wmma::fragment<wmma::matrix_b, 16, 16, 16, bf16, wmma::col_major> bhi, blo;
                wmma::load_matrix_sync(bhi, g_W2hi + (wx * 32 + j * 16) * HID + kk * 16, HID);
                wmma::load_matrix_sync(blo, g_W2lo + (wx * 32 + j * 16) * HID + kk * 16, HID);
                #pragma unroll
                for (int rf = 0; rf < 2; rf++) {
                    wmma::mma_sync(acc[rf][j], ahi[rf], bhi, acc[rf][j]);
                    wmma::mma_sync(acc[rf][j], alo[rf], bhi, acc[rf][j]);
                    wmma::mma_sync(acc[rf][j], ahi[rf], blo, acc[rf][j]);
                }
            }
        }
        #pragma unroll
        for (int rf = 0; rf < 2; rf++)
            #pragma unroll
            for (int j = 0; j < 2; j++) {
                wmma::store_matrix_sync(stg, acc[rf][j], 20, wmma::mem_row_major);
                __syncwarp();
                const int n = n0 + wy * 32 + rf * 16 + frow;
                const int b = n / Tn, tt = n % Tn;
                #pragma unroll
                for (int cc = 0; cc < 8; cc++) {
                    int e = wx * 32 + j * 16 + fcol + cc;
                    float v = fmaxf(stg[frow * 20 + fcol + cc] + b2[e], 0.0f);
                    bf16 hi = __float2bfloat16(v);
                    g_ench[(size_t)(tt * Bsz + b) * ENCD + e] = hi;
                    g_encl[(size_t)(tt * Bsz + b) * ENCD + e] = __float2bfloat16(v - __bfloat162float(hi));
                }
                __syncwarp();
            }
    }
}

// ================= v0 = enc[:,0] @ H_first =================
__global__ __launch_bounds__(256) void v0_kernel(const float* __restrict__ Hf) {
    __shared__ float hf_s[ENCD * Rr];
    __shared__ float enc_s[16][ENCD];
    const int tid = threadIdx.x;
    const int b0 = blockIdx.x * 16;
    for (int i = tid; i < ENCD * Rr; i += 256) hf_s[i] = Hf[i];
    for (int i = tid; i < 16 * ENCD; i += 256) {
        int j = i >> 7, e = i & 127;
        size_t a = (size_t)(b0 + j) * ENCD + e;
        enc_s[j][e] = __bfloat162float(g_ench[a]) + __bfloat162float(g_encl[a]);
    }
    __syncthreads();
    const int r = tid & 63, g = tid >> 6;
    for (int pass = 0; pass < 4; pass++) {
        int j = g * 4 + pass;
        float acc = 0.0f;
        for (int e = 0; e < ENCD; e++) acc += enc_s[j][e] * hf_s[e * 64 + r];
        g_v[0][(b0 + j) * 64 + r] = acc;
    }
}

// ================= chain v4: B-slice resident, A streamed =================
// grid (16 nb, 8 bg) x 256 threads. CTA: B slice 128k x 256n resident (hi/lo),
// streams 1024 batch rows in 32 chunks of 32 rows (A hi/lo + v), 2-stage cp.async.
// warp = 16 rows x 64 cols (one r, all p); per-chunk fused epilogue.
#define CBP4 264                                   // B row pad (bf16)
#define CAP4 136                                   // A row pad (bf16)
#define V4_BH 0u
#define V4_BL (V4_BH + 128u * CBP4 * 2u)           // 67584
#define V4_A  (V4_BL + 128u * CBP4 * 2u)           // 135168
#define A_STAGE (32u * CAP4 * 2u * 2u)             // Ah+Al per stage = 17408
#define V4_V  (V4_A + 2u * A_STAGE)                // 169984
#define V_STAGE (32u * 68u * 4u)                   // 8704
#define V4_ST (V4_V + 2u * V_STAGE)                // 187392
#define CH4_SMEM (V4_ST + 8u * 320u * 4u)          // 197632 B

__global__ __launch_bounds__(256, 1) void chain_res_kernel(int t) {
    extern __shared__ char smem[];
    bf16* Bh = (bf16*)(smem + V4_BH);
    bf16* Bl = (bf16*)(smem + V4_BL);
    float* stg_base = (float*)(smem + V4_ST);

    const int tid = threadIdx.x, wid = tid >> 5, lane = tid & 31;
    const int wy = wid >> 2, wx = wid & 3;         // wy 0..1 (16 rows), wx 0..3 (one r)
    const int nb = blockIdx.x;                     // n-block (256 cols)
    const int g0 = blockIdx.y * 1024;              // batch base of this CTA

    const bf16* Eh  = g_ench + (size_t)(t + 1) * Bsz * ENCD;
    const bf16* El  = g_encl + (size_t)(t + 1) * Bsz * ENCD;
    const bf16* HBh = g_HBh + (size_t)t * ENCD * 4096;
    const bf16* HBl = g_HBl + (size_t)t * ENCD * 4096;
    const float* vin  = g_v[t & 1];
    float*       vout = g_v[(t & 1) ^ 1];

    // ---- load B slice resident: 128 e-rows x 256 cols, hi+lo ----
    {
        const int cb = nb * 256;
        #pragma unroll
        for (int q = 0; q < 16; q++) {
            int i = tid + q * 256;
            int e = i >> 5, sl = (i & 31) * 8;
            cp16(smem_u32(Bh + e * CBP4 + sl), HBh + (size_t)e * 4096 + cb + sl);
            cp16(smem_u32(Bl + e * CBP4 + sl), HBl + (size_t)e * 4096 + cb + sl);
        }
        CP_COMMIT();
    }

    // ---- A/v chunk loader (32 rows) into stage s ----
    auto load_A = [&](int c, int s) {
        const int r0 = g0 + c * 32;
        bf16* Ah = (bf16*)(smem + V4_A + s * A_STAGE);
        bf16* Al = Ah + 32 * CAP4;
        float* vs = (float*)(smem + V4_V + s * V_STAGE);
        #pragma unroll
        for (int q = 0; q < 2; q++) {          // A hi/lo: 512 slots each
            int i = tid + q * 256;
            int r = i >> 4, sl = (i & 15) * 8;
            cp16(smem_u32(Ah + r * CAP4 + sl), Eh + (size_t)(r0 + r) * ENCD + sl);
            cp16(smem_u32(Al + r * CAP4 + sl), El + (size_t)(r0 + r) * ENCD + sl);
        }
        #pragma unroll
        for (int q = 0; q < 2; q++) {          // v: 512 slots of 4 floats
            int i = tid + q * 256;
            int r = i >> 4, sl = (i & 15) * 4;
            cp16(smem_u32(vs + r * 68 + sl), vin + (size_t)(r0 + r) * 64 + sl);
        }
        CP_COMMIT();
    };

    load_A(0, 0);

    float* stg = stg_base + wid * 320;
    const int frow = lane >> 1, half = lane & 1;
    const int r_glob = nb * 4 + wx;

    for (int c = 0; c < 32; c++) {
        const int s = c & 1;
        if (c < 31) { load_A(c + 1, s ^ 1); CP_WAIT(1); }
        else        { CP_WAIT(0); }
        __syncthreads();

        bf16* Ah = (bf16*)(smem + V4_A + s * A_STAGE);
        bf16* Al = Ah + 32 * CAP4;
        float* vs = (float*)(smem + V4_V + s * V_STAGE);

        wmma::fragment<wmma::accumulator, 16, 16, 16, float> acc[4];
        #pragma unroll
        for (int j = 0; j < 4; j++) wmma::fill_fragment(acc[j], 0.0f);

        #pragma unroll
        for (int kk = 0; kk < 8; kk++) {
            wmma::fragment<wmma::matrix_a, 16, 16, 16, bf16, wmma::row_major> ahi, alo;
            wmma::load_matrix_sync(ahi, Ah + (wy * 16) * CAP4 + kk * 16, CAP4);
            wmma::load_matrix_sync(alo, Al + (wy * 16) * CAP4 + kk * 16, CAP4);
            #pragma unroll
            for (int j = 0; j < 4; j++) {
                wmma::fragment<wmma::matrix_b, 16, 16, 16, bf16, wmma::row_major> bhi, blo;
                wmma::load_matrix_sync(bhi, Bh + (kk * 16) * CBP4 + wx * 64 + j * 16, CBP4);
                wmma::load_matrix_sync(blo, Bl + (kk * 16) * CBP4 + wx * 64 + j * 16, CBP4);
                wmma::mma_sync(acc[j], ahi, bhi, acc[j]);
                wmma::mma_sync(acc[j], alo, bhi, acc[j]);
                wmma::mma_sync(acc[j], ahi, blo, acc[j]);
            }
        }

        // fused epilogue: reduce over p against v, write vout rows of this chunk
        float racc = 0.f;
        #pragma unroll
        for (int j = 0; j < 4; j++) {
            wmma::store_matrix_sync(stg, acc[j], 20, wmma::mem_row_major);
            __syncwarp();
            const int p0 = j * 16 + half * 8;
            const int rl = wy * 16 + frow;
            float ssum = 0.f;
            #pragma unroll
            for (int cc = 0; cc < 8; cc++)
                ssum += stg[frow * 20 + half * 8 + cc] * vs[rl * 68 + p0 + cc];
            ssum += __shfl_xor_sync(0xffffffffu, ssum, 1);
            racc += ssum;
            __syncwarp();
        }
        if (half == 0) {
            int b = g0 + c * 32 + wy * 16 + frow;
            vout[(size_t)b * 64 + r_glob] = racc;
        }
        __syncthreads();
    }
}

// ================= final: out[b] = v . (H_last @ enc[:,T-1]) =================
__global__ __launch_bounds__(256) void final_kernel(const float* __restrict__ Hl,
                                                    float* __restrict__ out) {
    __shared__ float hl_t[ENCD * Rr];
    __shared__ float enc_s[16][ENCD];
    __shared__ float red2[16][2];
    const int tid = threadIdx.x;
    const int b0 = blockIdx.x * 16;
    for (int i = tid; i < ENCD * Rr; i += 256) {
        int e = i >> 6, p = i & 63;
        hl_t[i] = Hl[p * ENCD + e];
    }
    for (int i = tid; i < 16 * ENCD; i += 256) {
        int j = i >> 7, e = i & 127;
        size_t a = (size_t)((Tn - 1) * Bsz + b0 + j) * ENCD + e;
        enc_s[j][e] = __bfloat162float(g_ench[a]) + __bfloat162float(g_encl[a]);
    }
    __syncthreads();
    const int p = tid & 63, g = tid >> 6;
    const int warp = tid >> 5, half = warp & 1;
    for (int pass = 0; pass < 4; pass++) {
        int j = g * 4 + pass;
        float last = 0.0f;
        for (int e = 0; e < ENCD; e++) last += enc_s[j][e] * hl_t[e * 64 + p];
        float partial = g_v[0][(b0 + j) * 64 + p] * last;
        for (int off = 16; off > 0; off >>= 1)
            partial += __shfl_down_sync(0xffffffffu, partial, off);
        if ((tid & 31) == 0) red2[j][half] = partial;
    }
    __syncthreads();
    if (tid < 16) out[b0 + tid] = red2[tid][0] + red2[tid][1];
}

// ================= host launcher =================
extern "C" void kernel_launch(void* const* d_in, const int* in_sizes, int n_in,
                              void* d_out, int out_size) {
    const float* x  = (const float*)d_in[0];
    const float* W1 = (const float*)d_in[1];
    const float* b1 = (const float*)d_in[2];
    const float* W2 = (const float*)d_in[3];
    const float* b2 = (const float*)d_in[4];
    const float* Hf = (const float*)d_in[5];
    const float* Hm = (const float*)d_in[6];
    const float* Hl = (const float*)d_in[7];
    float* out = (float*)d_out;

    cudaFuncSetAttribute(encoder2_kernel,  cudaFuncAttributeMaxDynamicSharedMemorySize, ENC2_SMEM);
    cudaFuncSetAttribute(chain_res_kernel, cudaFuncAttributeMaxDynamicSharedMemorySize, CH4_SMEM);

    prep_w_kernel<<<96, 256>>>(W1, W2);
    prep_hb_kernel<<<(Tn - 2) * ENCD, 256>>>(Hm);
    encoder2_kernel<<<(Bsz * Tn) / 64, 256, ENC2_SMEM>>>(x, b1, b2);
    v0_kernel<<<Bsz / 16, 256>>>(Hf);
    for (int t = 0; t < Tn - 2; t++)
        chain_res_kernel<<<dim3(16, 8), 256, CH4_SMEM>>>(t);
    final_kernel<<<Bsz / 16, 256>>>(Hl, out);
}

// round 7
// speedup vs baseline: 1.0433x; 1.0433x over previous
#include <cuda_runtime.h>
#include <cuda_bf16.h>
#include <mma.h>
#include <cstdint>

using namespace nvcuda;
typedef __nv_bfloat16 bf16;

#define Bsz 8192
#define Tn  12
#define DIN 64
#define HID 512
#define ENCD 128
#define Rr  64

// ================= device-global scratch =================
__device__ __align__(256) bf16  g_ench[Tn * Bsz * ENCD];   // [t][b][e] hi
__device__ __align__(256) bf16  g_encl[Tn * Bsz * ENCD];   // lo
__device__ __align__(256) bf16  g_W1hi[HID * DIN],  g_W1lo[HID * DIN];
__device__ __align__(256) bf16  g_W2hi[ENCD * HID], g_W2lo[ENCD * HID];
// H_mid as GEMM-B: [t][e][n = r*64+p]
__device__ __align__(256) bf16  g_HBh[(Tn - 2) * ENCD * Rr * Rr];
__device__ __align__(256) bf16  g_HBl[(Tn - 2) * ENCD * Rr * Rr];

__device__ __forceinline__ uint32_t smem_u32(const void* p) {
    uint32_t a;
    asm("{ .reg .u64 t; cvta.to.shared.u64 t, %1; cvt.u32.u64 %0, t; }" : "=r"(a) : "l"(p));
    return a;
}
__device__ __forceinline__ void cp16(uint32_t dst, const void* src) {
    asm volatile("cp.async.cg.shared.global [%0], [%1], 16;" :: "r"(dst), "l"(src));
}
#define CP_COMMIT()  asm volatile("cp.async.commit_group;")
#define CP_WAIT(N)   asm volatile("cp.async.wait_group %0;" :: "n"(N))

// ================= prep: W splits =================
__global__ void prep_w_kernel(const float* __restrict__ W1,
                              const float* __restrict__ W2) {
    const int n1 = HID * DIN, n2 = ENCD * HID;
    for (int i = blockIdx.x * blockDim.x + threadIdx.x; i < n1 + n2;
         i += gridDim.x * blockDim.x) {
        const float* s; bf16 *h, *l; int j;
        if (i < n1) { s = W1; h = g_W1hi; l = g_W1lo; j = i; }
        else        { s = W2; h = g_W2hi; l = g_W2lo; j = i - n1; }
        float v = s[j];
        bf16 hi = __float2bfloat16(v);
        h[j] = hi;
        l[j] = __float2bfloat16(v - __bfloat162float(hi));
    }
}

// ================= prep: Hm[t,p,e,r] -> HB[t][e][r*64+p] hi/lo =================
__global__ __launch_bounds__(256) void prep_hb_kernel(const float* __restrict__ Hm) {
    __shared__ float tile[64][65];              // [p][r]
    const int t = blockIdx.x >> 7;
    const int e = blockIdx.x & 127;
    const int tid = threadIdx.x;
    for (int i = tid; i < 64 * 64; i += 256) {
        int p = i >> 6, r = i & 63;
        tile[p][r] = Hm[(((size_t)(t * 64 + p) * 128) + e) * 64 + r];
    }
    __syncthreads();
    bf16* dh = g_HBh + (size_t)(t * 128 + e) * 4096;
    bf16* dl = g_HBl + (size_t)(t * 128 + e) * 4096;
    for (int c = tid; c < 4096; c += 256) {
        int r = c >> 6, p = c & 63;
        float v = tile[p][r];
        bf16 hi = __float2bfloat16(v);
        dh[c] = hi;
        dl[c] = __float2bfloat16(v - __bfloat162float(hi));
    }
}

// ================= encoder v2 (unchanged) =================
#define EX_H 0u
#define EX_L (EX_H + 64u * 72u * 2u)
#define EH_H (EX_L + 64u * 72u * 2u)
#define EH_L (EH_H + 64u * 520u * 2u)
#define E_ST (EH_L + 64u * 520u * 2u)
#define ENC2_SMEM (E_ST + 8u * 320u * 4u)

__global__ __launch_bounds__(256, 1) void encoder2_kernel(const float* __restrict__ x,
                                                          const float* __restrict__ b1,
                                                          const float* __restrict__ b2) {
    extern __shared__ char smem[];
    bf16* xs_hi = (bf16*)(smem + EX_H);
    bf16* xs_lo = (bf16*)(smem + EX_L);
    bf16* hs_hi = (bf16*)(smem + EH_H);
    bf16* hs_lo = (bf16*)(smem + EH_L);
    float* stg_base = (float*)(smem + E_ST);

    const int tid = threadIdx.x, w = tid >> 5, lane = tid & 31;
    const int wy = w >> 2, wx = w & 3;
    const int n0 = blockIdx.x * 64;
    float* stg = stg_base + w * 320;
    const int frow = lane >> 1, fcol = (lane & 1) * 8;

    #pragma unroll
    for (int k = 0; k < 16; k++) {
        int idx = tid + k * 256;
        int r = idx >> 6, c = idx & 63;
        float v = x[(size_t)(n0 + r) * DIN + c];
        bf16 hi = __float2bfloat16(v);
        xs_hi[r * 72 + c] = hi;
        xs_lo[r * 72 + c] = __float2bfloat16(v - __bfloat162float(hi));
    }
    __syncthreads();

    #pragma unroll
    for (int pass = 0; pass < 2; pass++) {
        const int cb = wx * 128 + pass * 64;
        wmma::fragment<wmma::accumulator, 16, 16, 16, float> acc[2][4];
        #pragma unroll
        for (int rf = 0; rf < 2; rf++)
            #pragma unroll
            for (int j = 0; j < 4; j++) wmma::fill_fragment(acc[rf][j], 0.0f);
        #pragma unroll
        for (int kk = 0; kk < 4; kk++) {
            wmma::fragment<wmma::matrix_a, 16, 16, 16, bf16, wmma::row_major> ahi[2], alo[2];
            #pragma unroll
            for (int rf = 0; rf < 2; rf++) {
                wmma::load_matrix_sync(ahi[rf], xs_hi + (wy * 32 + rf * 16) * 72 + kk * 16, 72);
                wmma::load_matrix_sync(alo[rf], xs_lo + (wy * 32 + rf * 16) * 72 + kk * 16, 72);
            }
            #pragma unroll
            for (int j = 0; j < 4; j++) {
                wmma::fragment<wmma::matrix_b, 16, 16, 16, bf16, wmma::col_major> bhi, blo;
                wmma::load_matrix_sync(bhi, g_W1hi + (cb + j * 16) * DIN + kk * 16, DIN);
                wmma::load_matrix_sync(blo, g_W1lo + (cb + j * 16) * DIN + kk * 16, DIN);
                #pragma unroll
                for (int rf = 0; rf < 2; rf++) {
                    wmma::mma_sync(acc[rf][j], ahi[rf], bhi, acc[rf][j]);
                    wmma::mma_sync(acc[rf][j], alo[rf], bhi, acc[rf][j]);
                    wmma::mma_sync(acc[rf][j], ahi[rf], blo, acc[rf][j]);
                }
            }
        }
        #pragma unroll
        for (int rf = 0; rf < 2; rf++)
            #pragma unroll
            for (int j = 0; j < 4; j++) {
                wmma::store_matrix_sync(stg, acc[rf][j], 20, wmma::mem_row_major);
                __syncwarp();
                const int rbase = wy * 32 + rf * 16 + frow;
                #pragma unroll
                for (int cc = 0; cc < 8; cc++) {
                    int gc = cb + j * 16 + fcol + cc;
                    float v = fmaxf(stg[frow * 20 + fcol + cc] + b1[gc], 0.0f);
                    bf16 hi = __float2bfloat16(v);
                    hs_hi[rbase * 520 + gc] = hi;
                    hs_lo[rbase * 520 + gc] = __float2bfloat16(v - __bfloat162float(hi));
                }
                __syncwarp();
            }
    }
    __syncthreads();

    {
        wmma::fragment<wmma::accumulator, 16, 16, 16, float> acc[2][2];
        #pragma unroll
        for (int rf = 0; rf < 2; rf++)
            #pragma unroll
            for (int j = 0; j < 2; j++) wmma::fill_fragment(acc[rf][j], 0.0f);
        #pragma unroll 8
        for (int kk = 0; kk < 32; kk++) {
            wmma::fragment<wmma::matrix_a, 16, 16, 16, bf16, wmma::row_major> ahi[2], alo[2];
            #pragma unroll
            for (int rf = 0; rf < 2; rf++) {
                wmma::load_matrix_sync(ahi[rf], hs_hi + (wy * 32 + rf * 16) * 520 + kk * 16, 520);
                wmma::load_matrix_sync(alo[rf], hs_lo + (wy * 32 + rf * 16) * 520 + kk * 16, 520);
            }
            #pragma unroll
            for (int j = 0; j < 2; j++) {
                wmma::fragment<wmma::matrix_b, 16, 16, 16, bf16, wmma::col_major> bhi, blo;
                wmma::load_matrix_sync(bhi, g_W2hi + (wx * 32 + j * 16) * HID + kk * 16, HID);
                wmma::load_matrix_sync(blo, g_W2lo + (wx * 32 + j * 16) * HID + kk * 16, HID);
                #pragma unroll
                for (int rf = 0; rf < 2; rf++) {
                    wmma::mma_sync(acc[rf][j], ahi[rf], bhi, acc[rf][j]);
                    wmma::mma_sync(acc[rf][j], alo[rf], bhi, acc[rf][j]);
                    wmma::mma_sync(acc[rf][j], ahi[rf], blo, acc[rf][j]);
                }
            }
        }
        #pragma unroll
        for (int rf = 0; rf < 2; rf++)
            #pragma unroll
            for (int j = 0; j < 2; j++) {
                wmma::store_matrix_sync(stg, acc[rf][j], 20, wmma::mem_row_major);
                __syncwarp();
                const int n = n0 + wy * 32 + rf * 16 + frow;
                const int b = n / Tn, tt = n % Tn;
                #pragma unroll
                for (int cc = 0; cc < 8; cc++) {
                    int e = wx * 32 + j * 16 + fcol + cc;
                    float v = fmaxf(stg[frow * 20 + fcol + cc] + b2[e], 0.0f);
                    bf16 hi = __float2bfloat16(v);
                    g_ench[(size_t)(tt * Bsz + b) * ENCD + e] = hi;
                    g_encl[(size_t)(tt * Bsz + b) * ENCD + e] = __float2bfloat16(v - __bfloat162float(hi));
                }
                __syncwarp();
            }
    }
}

// ================= fused chain: v0 + 10 steps + final in one kernel =================
// 128 CTAs x 256 threads; CTA owns 64 batch rows; v lives in SMEM ping-pong.
// Per step: A (enc hi/lo) resident, B streamed in 64 chunks (32k x 256n) via
// 3-stage cp.async pipeline that runs continuously across steps.
#define CAPF 136
#define CBPF 264
#define F_AH 0u
#define F_AL (F_AH + 64u * CAPF * 2u)               // 17408
#define F_V  (F_AL + 64u * CAPF * 2u)               // 34816
#define F_ST (F_V + 2u * 64u * 65u * 4u)            // 68096
#define F_B  (F_ST + 8u * 320u * 4u)                // 78336
#define B_STG_B (32u * CBPF * 2u * 2u)              // hi+lo per stage = 33792
#define CHF_SMEM (F_B + 3u * B_STG_B)               // 179712 B

__global__ __launch_bounds__(256, 1) void chain_fused_kernel(const float* __restrict__ Hf,
                                                             const float* __restrict__ Hl,
                                                             float* __restrict__ out) {
    extern __shared__ char smem[];
    bf16* As_h = (bf16*)(smem + F_AH);
    bf16* As_l = (bf16*)(smem + F_AL);
    float* v_s[2] = { (float*)(smem + F_V), (float*)(smem + F_V) + 64 * 65 };
    float* stg_base = (float*)(smem + F_ST);
    float* scr1 = (float*)(smem + F_B);              // 8192 floats (endpoint H)
    float* scr2 = scr1 + 8192;                       // 8192 floats (endpoint enc fp32)

    const int tid = threadIdx.x, wid = tid >> 5, lane = tid & 31;
    const int wy = wid >> 2, wx = wid & 3;
    const int b0 = blockIdx.x * 64;

    // -------- B chunk async loader: gi = t*64 + g, stage = gi % 3 --------
    auto load_B = [&](int gi) {
        const int tt = gi >> 6, g = gi & 63;
        const int nb = g >> 2, kc = g & 3;
        const int k0 = kc * 32, cb = nb * 256;
        const bf16* HBh = g_HBh + (size_t)tt * ENCD * 4096;
        const bf16* HBl = g_HBl + (size_t)tt * ENCD * 4096;
        char* stp = smem + F_B + (uint32_t)(gi % 3) * B_STG_B;
        bf16* Bh = (bf16*)stp;
        bf16* Bl = Bh + 32 * CBPF;
        #pragma unroll
        for (int q = 0; q < 4; q++) {
            int i = tid + q * 256;
            int e = i >> 5, sl = (i & 31) * 8;
            cp16(smem_u32(Bh + e * CBPF + sl), HBh + (size_t)(k0 + e) * 4096 + cb + sl);
            cp16(smem_u32(Bl + e * CBPF + sl), HBl + (size_t)(k0 + e) * 4096 + cb + sl);
        }
        CP_COMMIT();
    };
    // -------- A (enc plane) loader, plain LDG/STS --------
    auto load_A = [&](int plane) {
        const bf16* Eh = g_ench + (size_t)plane * Bsz * ENCD;
        const bf16* El = g_encl + (size_t)plane * Bsz * ENCD;
        #pragma unroll
        for (int k = 0; k < 4; k++) {
            int i = tid + k * 256;
            int r = i >> 4, sl = (i & 15) * 8;
            *(uint4*)(As_h + r * CAPF + sl) = *(const uint4*)(Eh + (size_t)(b0 + r) * ENCD + sl);
            *(uint4*)(As_l + r * CAPF + sl) = *(const uint4*)(El + (size_t)(b0 + r) * ENCD + sl);
        }
    };

    // ======== v0: v_s[0][b,r] = sum_e enc0[b,e] * Hf[e,r]  (fp32 SIMT) ========
    for (int i = tid; i < ENCD * Rr; i += 256) scr1[i] = Hf[i];   // [e*64+r]
    {
        const bf16* Eh = g_ench;  const bf16* El = g_encl;        // plane 0
        for (int i = tid; i < 64 * ENCD; i += 256) {
            int r = i >> 7, e = i & 127;
            size_t a = (size_t)(b0 + r) * ENCD + e;
            scr2[r * 128 + e] = __bfloat162float(Eh[a]) + __bfloat162float(El[a]);
        }
    }
    __syncthreads();
    {
        const int r = tid & 63, q = tid >> 6;
        #pragma unroll
        for (int rr = 0; rr < 16; rr++) {
            int row = q * 16 + rr;
            float acc = 0.f;
            #pragma unroll 8
            for (int e = 0; e < ENCD; e++) acc += scr2[row * 128 + e] * scr1[e * 64 + r];
            v_s[0][row * 65 + r] = acc;
        }
    }
    __syncthreads();   // scratch free; v0 ready

    // ======== chain steps ========
    load_A(1);                 // enc plane for t=0
    load_B(0); load_B(1);      // pipeline prologue

    float* stg = stg_base + wid * 320;
    const int frow = lane >> 1, half = lane & 1;
    int cur = 0;

    wmma::fragment<wmma::accumulator, 16, 16, 16, float> acc[2][4];
    #pragma unroll
    for (int rf = 0; rf < 2; rf++)
        #pragma unroll
        for (int j = 0; j < 4; j++) wmma::fill_fragment(acc[rf][j], 0.0f);

    for (int t = 0; t < Tn - 2; t++) {
        if (t > 0) {
            __syncthreads();       // all warps done with previous step (A + v writes)
            load_A(t + 1);
        }
        for (int g = 0; g < 64; g++) {
            const int gi = t * 64 + g;
            if (gi == 639) { CP_WAIT(0); } else { CP_WAIT(1); }
            __syncthreads();                        // stage gi ready; stage gi-1 reads done
            if (gi + 2 < 640) load_B(gi + 2);       // overwrites stage (gi-1)%3 — safe now

            char* stp = smem + F_B + (uint32_t)(gi % 3) * B_STG_B;
            bf16* Bh = (bf16*)stp;
            bf16* Bl = Bh + 32 * CBPF;
            const int k0 = (g & 3) * 32;
            #pragma unroll
            for (int kk = 0; kk < 2; kk++) {
                wmma::fragment<wmma::matrix_a, 16, 16, 16, bf16, wmma::row_major> ahi[2], alo[2];
                #pragma unroll
                for (int rf = 0; rf < 2; rf++) {
                    wmma::load_matrix_sync(ahi[rf], As_h + (wy * 32 + rf * 16) * CAPF + k0 + kk * 16, CAPF);
                    wmma::load_matrix_sync(alo[rf], As_l + (wy * 32 + rf * 16) * CAPF + k0 + kk * 16, CAPF);
                }
                #pragma unroll
                for (int j = 0; j < 4; j++) {
                    wmma::fragment<wmma::matrix_b, 16, 16, 16, bf16, wmma::row_major> bhi, blo;
                    wmma::load_matrix_sync(bhi, Bh + (kk * 16) * CBPF + wx * 64 + j * 16, CBPF);
                    wmma::load_matrix_sync(blo, Bl + (kk * 16) * CBPF + wx * 64 + j * 16, CBPF);
                    #pragma unroll
                    for (int rf = 0; rf < 2; rf++) {
                        wmma::mma_sync(acc[rf][j], ahi[rf], bhi, acc[rf][j]);
                        wmma::mma_sync(acc[rf][j], alo[rf], bhi, acc[rf][j]);
                        wmma::mma_sync(acc[rf][j], ahi[rf], blo, acc[rf][j]);
                    }
                }
            }

            if ((g & 3) == 3) {
                // epilogue for n-block nb: reduce over p against v_s[cur], write v_s[cur^1]
                const int nb = g >> 2;
                const int r_loc = nb * 4 + wx;
                float* vcur = v_s[cur];
                float* vnxt = v_s[cur ^ 1];
                #pragma unroll
                for (int rf = 0; rf < 2; rf++) {
                    float racc = 0.f;
                    #pragma unroll
                    for (int j = 0; j < 4; j++) {
                        wmma::store_matrix_sync(stg, acc[rf][j], 20, wmma::mem_row_major);
                        __syncwarp();
                        const int p0 = j * 16 + half * 8;
                        const int bl = wy * 32 + rf * 16 + frow;
                        float ssum = 0.f;
                        #pragma unroll
                        for (int cc = 0; cc < 8; cc++)
                            ssum += stg[frow * 20 + half * 8 + cc] * vcur[bl * 65 + p0 + cc];
                        ssum += __shfl_xor_sync(0xffffffffu, ssum, 1);
                        racc += ssum;
                        __syncwarp();
                        wmma::fill_fragment(acc[rf][j], 0.0f);
                    }
                    if (half == 0) {
                        int bl = wy * 32 + rf * 16 + frow;
                        vnxt[bl * 65 + r_loc] = racc;
                    }
                }
            }
        }
        cur ^= 1;
    }

    // ======== final: out[b] = sum_p v[b,p] * (sum_e enc11[b,e] * Hl[p,e]) ========
    __syncthreads();           // B stages free, v final ready in v_s[cur]
    for (int i = tid; i < ENCD * Rr; i += 256) {
        int e = i >> 6, p = i & 63;
        scr1[i] = Hl[p * ENCD + e];                 // transposed [e*64+p]
    }
    {
        const bf16* Eh = g_ench + (size_t)(Tn - 1) * Bsz * ENCD;
        const bf16* El = g_encl + (size_t)(Tn - 1) * Bsz * ENCD;
        for (int i = tid; i < 64 * ENCD; i += 256) {
            int r = i >> 7, e = i & 127;
            size_t a = (size_t)(b0 + r) * ENCD + e;
            scr2[r * 128 + e] = __bfloat162float(Eh[a]) + __bfloat162float(El[a]);
        }
    }
    __syncthreads();
    {
        float* red = stg_base;                       // 64 x 4
        const int row = tid >> 2, q = tid & 3;
        float partial = 0.f;
        #pragma unroll
        for (int pp = 0; pp < 16; pp++) {
            int p = q * 16 + pp;
            float last = 0.f;
            #pragma unroll 8
            for (int e = 0; e < ENCD; e++) last += scr2[row * 128 + e] * scr1[e * 64 + p];
            partial += v_s[cur][row * 65 + p] * last;
        }
        red[row * 4 + q] = partial;
        __syncthreads();
        if (tid < 64)
            out[b0 + tid] = red[tid * 4 + 0] + red[tid * 4 + 1]
                          + red[tid * 4 + 2] + red[tid * 4 + 3];
    }
}

// ================= host launcher =================
extern "C" void kernel_launch(void* const* d_in, const int* in_sizes, int n_in,
                              void* d_out, int out_size) {
    const float* x  = (const float*)d_in[0];
    const float* W1 = (const float*)d_in[1];
    const float* b1 = (const float*)d_in[2];
    const float* W2 = (const float*)d_in[3];
    const float* b2 = (const float*)d_in[4];
    const float* Hf = (const float*)d_in[5];
    const float* Hm = (const float*)d_in[6];
    const float* Hl = (const float*)d_in[7];
    float* out = (float*)d_out;

    cudaFuncSetAttribute(encoder2_kernel,    cudaFuncAttributeMaxDynamicSharedMemorySize, ENC2_SMEM);
    cudaFuncSetAttribute(chain_fused_kernel, cudaFuncAttributeMaxDynamicSharedMemorySize, CHF_SMEM);

    prep_w_kernel<<<96, 256>>>(W1, W2);
    prep_hb_kernel<<<(Tn - 2) * ENCD, 256>>>(Hm);
    encoder2_kernel<<<(Bsz * Tn) / 64, 256, ENC2_SMEM>>>(x, b1, b2);
    chain_fused_kernel<<<128, 256, CHF_SMEM>>>(Hf, Hl, out);
}

// round 8
// speedup vs baseline: 1.3620x; 1.3055x over previous
#include <cuda_runtime.h>
#include <cuda_bf16.h>
#include <mma.h>
#include <cstdint>

using namespace nvcuda;
typedef __nv_bfloat16 bf16;

#define Bsz 8192
#define Tn  12
#define DIN 64
#define HID 512
#define ENCD 128
#define Rr  64

// ================= device-global scratch =================
__device__ __align__(256) bf16  g_ench[Tn * Bsz * ENCD];   // [t][b][e] hi
__device__ __align__(256) bf16  g_encl[Tn * Bsz * ENCD];   // lo
__device__ __align__(256) bf16  g_W1hi[HID * DIN],  g_W1lo[HID * DIN];
__device__ __align__(256) bf16  g_W2hi[ENCD * HID], g_W2lo[ENCD * HID];
// H_mid as GEMM-B: [t][e][n = r*64+p]
__device__ __align__(256) bf16  g_HBh[(Tn - 2) * ENCD * Rr * Rr];
__device__ __align__(256) bf16  g_HBl[(Tn - 2) * ENCD * Rr * Rr];

__device__ __forceinline__ uint32_t smem_u32(const void* p) {
    uint32_t a;
    asm("{ .reg .u64 t; cvta.to.shared.u64 t, %1; cvt.u32.u64 %0, t; }" : "=r"(a) : "l"(p));
    return a;
}
__device__ __forceinline__ void cp16(uint32_t dst, const void* src) {
    asm volatile("cp.async.cg.shared.global [%0], [%1], 16;" :: "r"(dst), "l"(src));
}
#define CP_COMMIT()  asm volatile("cp.async.commit_group;")
#define CP_WAIT(N)   asm volatile("cp.async.wait_group %0;" :: "n"(N))

// ---- raw MMA primitives (sm_80-compatible, lower to HMMA.16816) ----
__device__ __forceinline__ void ldmx4(uint32_t* r, uint32_t a) {
    asm volatile("ldmatrix.sync.aligned.m8n8.x4.shared.b16 {%0,%1,%2,%3}, [%4];"
                 : "=r"(r[0]), "=r"(r[1]), "=r"(r[2]), "=r"(r[3]) : "r"(a));
}
__device__ __forceinline__ void ldmx4t(uint32_t* r, uint32_t a) {
    asm volatile("ldmatrix.sync.aligned.m8n8.x4.trans.shared.b16 {%0,%1,%2,%3}, [%4];"
                 : "=r"(r[0]), "=r"(r[1]), "=r"(r[2]), "=r"(r[3]) : "r"(a));
}
__device__ __forceinline__ void mma16816(float* d, const uint32_t* a, const uint32_t* b) {
    asm volatile("mma.sync.aligned.m16n8k16.row.col.f32.bf16.bf16.f32 "
                 "{%0,%1,%2,%3}, {%4,%5,%6,%7}, {%8,%9}, {%0,%1,%2,%3};"
                 : "+f"(d[0]), "+f"(d[1]), "+f"(d[2]), "+f"(d[3])
                 : "r"(a[0]), "r"(a[1]), "r"(a[2]), "r"(a[3]), "r"(b[0]), "r"(b[1]));
}

// ================= prep: W splits =================
__global__ void prep_w_kernel(const float* __restrict__ W1,
                              const float* __restrict__ W2) {
    const int n1 = HID * DIN, n2 = ENCD * HID;
    for (int i = blockIdx.x * blockDim.x + threadIdx.x; i < n1 + n2;
         i += gridDim.x * blockDim.x) {
        const float* s; bf16 *h, *l; int j;
        if (i < n1) { s = W1; h = g_W1hi; l = g_W1lo; j = i; }
        else        { s = W2; h = g_W2hi; l = g_W2lo; j = i - n1; }
        float v = s[j];
        bf16 hi = __float2bfloat16(v);
        h[j] = hi;
        l[j] = __float2bfloat16(v - __bfloat162float(hi));
    }
}

// ================= prep: Hm[t,p,e,r] -> HB[t][e][r*64+p] hi/lo =================
__global__ __launch_bounds__(256) void prep_hb_kernel(const float* __restrict__ Hm) {
    __shared__ float tile[64][65];              // [p][r]
    const int t = blockIdx.x >> 7;
    const int e = blockIdx.x & 127;
    const int tid = threadIdx.x;
    for (int i = tid; i < 64 * 64; i += 256) {
        int p = i >> 6, r = i & 63;
        tile[p][r] = Hm[(((size_t)(t * 64 + p) * 128) + e) * 64 + r];
    }
    __syncthreads();
    bf16* dh = g_HBh + (size_t)(t * 128 + e) * 4096;
    bf16* dl = g_HBl + (size_t)(t * 128 + e) * 4096;
    for (int c = tid; c < 4096; c += 256) {
        int r = c >> 6, p = c & 63;
        float v = tile[p][r];
        bf16 hi = __float2bfloat16(v);
        dh[c] = hi;
        dl[c] = __float2bfloat16(v - __bfloat162float(hi));
    }
}

// ================= encoder v2 (unchanged) =================
#define EX_H 0u
#define EX_L (EX_H + 64u * 72u * 2u)
#define EH_H (EX_L + 64u * 72u * 2u)
#define EH_L (EH_H + 64u * 520u * 2u)
#define E_ST (EH_L + 64u * 520u * 2u)
#define ENC2_SMEM (E_ST + 8u * 320u * 4u)

__global__ __launch_bounds__(256, 1) void encoder2_kernel(const float* __restrict__ x,
                                                          const float* __restrict__ b1,
                                                          const float* __restrict__ b2) {
    extern __shared__ char smem[];
    bf16* xs_hi = (bf16*)(smem + EX_H);
    bf16* xs_lo = (bf16*)(smem + EX_L);
    bf16* hs_hi = (bf16*)(smem + EH_H);
    bf16* hs_lo = (bf16*)(smem + EH_L);
    float* stg_base = (float*)(smem + E_ST);

    const int tid = threadIdx.x, w = tid >> 5, lane = tid & 31;
    const int wy = w >> 2, wx = w & 3;
    const int n0 = blockIdx.x * 64;
    float* stg = stg_base + w * 320;
    const int frow = lane >> 1, fcol = (lane & 1) * 8;

    #pragma unroll
    for (int k = 0; k < 16; k++) {
        int idx = tid + k * 256;
        int r = idx >> 6, c = idx & 63;
        float v = x[(size_t)(n0 + r) * DIN + c];
        bf16 hi = __float2bfloat16(v);
        xs_hi[r * 72 + c] = hi;
        xs_lo[r * 72 + c] = __float2bfloat16(v - __bfloat162float(hi));
    }
    __syncthreads();

    #pragma unroll
    for (int pass = 0; pass < 2; pass++) {
        const int cb = wx * 128 + pass * 64;
        wmma::fragment<wmma::accumulator, 16, 16, 16, float> acc[2][4];
        #pragma unroll
        for (int rf = 0; rf < 2; rf++)
            #pragma unroll
            for (int j = 0; j < 4; j++) wmma::fill_fragment(acc[rf][j], 0.0f);
        #pragma unroll
        for (int kk = 0; kk < 4; kk++) {
            wmma::fragment<wmma::matrix_a, 16, 16, 16, bf16, wmma::row_major> ahi[2], alo[2];
            #pragma unroll
            for (int rf = 0; rf < 2; rf++) {
                wmma::load_matrix_sync(ahi[rf], xs_hi + (wy * 32 + rf * 16) * 72 + kk * 16, 72);
                wmma::load_matrix_sync(alo[rf], xs_lo + (wy * 32 + rf * 16) * 72 + kk * 16, 72);
            }
            #pragma unroll
            for (int j = 0; j < 4; j++) {
                wmma::fragment<wmma::matrix_b, 16, 16, 16, bf16, wmma::col_major> bhi, blo;
                wmma::load_matrix_sync(bhi, g_W1hi + (cb + j * 16) * DIN + kk * 16, DIN);
                wmma::load_matrix_sync(blo, g_W1lo + (cb + j * 16) * DIN + kk * 16, DIN);
                #pragma unroll
                for (int rf = 0; rf < 2; rf++) {
                    wmma::mma_sync(acc[rf][j], ahi[rf], bhi, acc[rf][j]);
                    wmma::mma_sync(acc[rf][j], alo[rf], bhi, acc[rf][j]);
                    wmma::mma_sync(acc[rf][j], ahi[rf], blo, acc[rf][j]);
                }
            }
        }
        #pragma unroll
        for (int rf = 0; rf < 2; rf++)
            #pragma unroll
            for (int j = 0; j < 4; j++) {
                wmma::store_matrix_sync(stg, acc[rf][j], 20, wmma::mem_row_major);
                __syncwarp();
                const int rbase = wy * 32 + rf * 16 + frow;
                #pragma unroll
                for (int cc = 0; cc < 8; cc++) {
                    int gc = cb + j * 16 + fcol + cc;
                    float v = fmaxf(stg[frow * 20 + fcol + cc] + b1[gc], 0.0f);
                    bf16 hi = __float2bfloat16(v);
                    hs_hi[rbase * 520 + gc] = hi;
                    hs_lo[rbase * 520 + gc] = __float2bfloat16(v - __bfloat162float(hi));
                }
                __syncwarp();
            }
    }
    __syncthreads();

    {
        wmma::fragment<wmma::accumulator, 16, 16, 16, float> acc[2][2];
        #pragma unroll
        for (int rf = 0; rf < 2; rf++)
            #pragma unroll
            for (int j = 0; j < 2; j++) wmma::fill_fragment(acc[rf][j], 0.0f);
        #pragma unroll 8
        for (int kk = 0; kk < 32; kk++) {
            wmma::fragment<wmma::matrix_a, 16, 16, 16, bf16, wmma::row_major> ahi[2], alo[2];
            #pragma unroll
            for (int rf = 0; rf < 2; rf++) {
                wmma::load_matrix_sync(ahi[rf], hs_hi + (wy * 32 + rf * 16) * 520 + kk * 16, 520);
                wmma::load_matrix_sync(alo[rf], hs_lo + (wy * 32 + rf * 16) * 520 + kk * 16, 520);
            }
            #pragma unroll
            for (int j = 0; j < 2; j++) {
                wmma::fragment<wmma::matrix_b, 16, 16, 16, bf16, wmma::col_major> bhi, blo;
                wmma::load_matrix_sync(bhi, g_W2hi + (wx * 32 + j * 16) * HID + kk * 16, HID);
                wmma::load_matrix_sync(blo, g_W2lo + (wx * 32 + j * 16) * HID + kk * 16, HID);
                #pragma unroll
                for (int rf = 0; rf < 2; rf++) {
                    wmma::mma_sync(acc[rf][j], ahi[rf], bhi, acc[rf][j]);
                    wmma::mma_sync(acc[rf][j], alo[rf], bhi, acc[rf][j]);
                    wmma::mma_sync(acc[rf][j], ahi[rf], blo, acc[rf][j]);
                }
            }
        }
        #pragma unroll
        for (int rf = 0; rf < 2; rf++)
            #pragma unroll
            for (int j = 0; j < 2; j++) {
                wmma::store_matrix_sync(stg, acc[rf][j], 20, wmma::mem_row_major);
                __syncwarp();
                const int n = n0 + wy * 32 + rf * 16 + frow;
                const int b = n / Tn, tt = n % Tn;
                #pragma unroll
                for (int cc = 0; cc < 8; cc++) {
                    int e = wx * 32 + j * 16 + fcol + cc;
                    float v = fmaxf(stg[frow * 20 + fcol + cc] + b2[e], 0.0f);
                    bf16 hi = __float2bfloat16(v);
                    g_ench[(size_t)(tt * Bsz + b) * ENCD + e] = hi;
                    g_encl[(size_t)(tt * Bsz + b) * ENCD + e] = __float2bfloat16(v - __bfloat162float(hi));
                }
                __syncwarp();
            }
    }
}

// ================= fused chain (mma.sync, register epilogue) =================
// 128 CTAs x 256 threads (8 warps, 2x4). CTA: 64 batch rows; v in SMEM ping-pong.
// B streamed 32k x 256n chunks via 4-stage cp.async; A resident per step.
#define CAPF 136
#define CBPF 264
#define F_AH 0u
#define F_AL (F_AH + 64u * CAPF * 2u)               // 17408
#define F_V  (F_AL + 64u * CAPF * 2u)               // 34816
#define F_B  (F_V + 2u * 64u * 72u * 4u)            // 71680
#define B_STG_B (32u * CBPF * 2u * 2u)              // hi+lo per stage = 33792
#define CHF_SMEM (F_B + 4u * B_STG_B)               // 206848 B

__global__ __launch_bounds__(256, 1) void chain_mma_kernel(const float* __restrict__ Hf,
                                                           const float* __restrict__ Hl,
                                                           float* __restrict__ out) {
    extern __shared__ char smem[];
    bf16* As_h = (bf16*)(smem + F_AH);
    bf16* As_l = (bf16*)(smem + F_AL);
    float* v_s[2] = { (float*)(smem + F_V), (float*)(smem + F_V) + 64 * 72 };
    float* scr1 = (float*)(smem + F_B);              // endpoint scratch (inside B region)
    float* scr2 = scr1 + 8192;

    const int tid = threadIdx.x, wid = tid >> 5, lane = tid & 31;
    const int wy = wid >> 2, wx = wid & 3;
    const int b0 = blockIdx.x * 64;

    auto load_B = [&](int gi) {
        const int tt = gi >> 6, g = gi & 63;
        const int nb = g >> 2, kc = g & 3;
        const int k0 = kc * 32, cb = nb * 256;
        const bf16* HBh = g_HBh + (size_t)tt * ENCD * 4096;
        const bf16* HBl = g_HBl + (size_t)tt * ENCD * 4096;
        char* stp = smem + F_B + (uint32_t)(gi & 3) * B_STG_B;
        bf16* Bh = (bf16*)stp;
        bf16* Bl = Bh + 32 * CBPF;
        #pragma unroll
        for (int q = 0; q < 4; q++) {
            int i = tid + q * 256;
            int e = i >> 5, sl = (i & 31) * 8;
            cp16(smem_u32(Bh + e * CBPF + sl), HBh + (size_t)(k0 + e) * 4096 + cb + sl);
            cp16(smem_u32(Bl + e * CBPF + sl), HBl + (size_t)(k0 + e) * 4096 + cb + sl);
        }
        CP_COMMIT();
    };
    auto load_A = [&](int plane) {
        const bf16* Eh = g_ench + (size_t)plane * Bsz * ENCD;
        const bf16* El = g_encl + (size_t)plane * Bsz * ENCD;
        #pragma unroll
        for (int k = 0; k < 4; k++) {
            int i = tid + k * 256;
            int r = i >> 4, sl = (i & 15) * 8;
            *(uint4*)(As_h + r * CAPF + sl) = *(const uint4*)(Eh + (size_t)(b0 + r) * ENCD + sl);
            *(uint4*)(As_l + r * CAPF + sl) = *(const uint4*)(El + (size_t)(b0 + r) * ENCD + sl);
        }
    };

    // ======== v0 (fp32 SIMT, scratch in B region) ========
    for (int i = tid; i < ENCD * Rr; i += 256) scr1[i] = Hf[i];   // [e*64+r]
    for (int i = tid; i < 64 * ENCD; i += 256) {
        int r = i >> 7, e = i & 127;
        size_t a = (size_t)(b0 + r) * ENCD + e;
        scr2[r * 128 + e] = __bfloat162float(g_ench[a]) + __bfloat162float(g_encl[a]);
    }
    __syncthreads();
    {
        const int r = tid & 63, q = tid >> 6;
        #pragma unroll
        for (int rr = 0; rr < 16; rr++) {
            int row = q * 16 + rr;
            float acc = 0.f;
            #pragma unroll 8
            for (int e = 0; e < ENCD; e++) acc += scr2[row * 128 + e] * scr1[e * 64 + r];
            v_s[0][row * 72 + r] = acc;
        }
    }
    __syncthreads();   // scratch free

    // ======== pipeline prologue ========
    load_A(1);
    load_B(0); load_B(1); load_B(2);
    int cur = 0;

    float d[2][8][4];
    #pragma unroll
    for (int rf = 0; rf < 2; rf++)
        #pragma unroll
        for (int j = 0; j < 8; j++)
            #pragma unroll
            for (int q = 0; q < 4; q++) d[rf][j][q] = 0.f;

    // per-lane fragment address components
    const int a_row = (lane & 15);
    const int a_kof = (lane >> 4) << 3;
    const int b_row = (lane & 7) + ((lane >> 3) & 1) * 8;
    const int b_nof = (lane >> 4) << 3;

    for (int t = 0; t < Tn - 2; t++) {
        if (t > 0) {
            __syncthreads();           // all compute of step t-1 done
            load_A(t + 1);             // enc plane for step t
            __syncthreads();
        }
        for (int g = 0; g < 64; g++) {
            const int gi = t * 64 + g;
            if (gi < 638)      { CP_WAIT(2); }
            else if (gi == 638){ CP_WAIT(1); }
            else               { CP_WAIT(0); }
            __syncthreads();                       // stage gi ready; stage gi-1 consumed
            if (gi + 3 < 640) load_B(gi + 3);      // overwrites stage (gi-1)&3 — safe

            char* stp = smem + F_B + (uint32_t)(gi & 3) * B_STG_B;
            bf16* Bh = (bf16*)stp;
            bf16* Bl = Bh + 32 * CBPF;
            const int k0 = (g & 3) * 32;

            #pragma unroll
            for (int kk = 0; kk < 2; kk++) {
                uint32_t ah[2][4], al[2][4];
                #pragma unroll
                for (int rf = 0; rf < 2; rf++) {
                    int arow = wy * 32 + rf * 16 + a_row;
                    int acol = k0 + kk * 16 + a_kof;
                    ldmx4(ah[rf], smem_u32(As_h + arow * CAPF + acol));
                    ldmx4(al[rf], smem_u32(As_l + arow * CAPF + acol));
                }
                #pragma unroll
                for (int jj = 0; jj < 4; jj++) {
                    int brow = kk * 16 + b_row;
                    int bcol = wx * 64 + jj * 16 + b_nof;
                    uint32_t bh[4], bl[4];
                    ldmx4t(bh, smem_u32(Bh + brow * CBPF + bcol));
                    ldmx4t(bl, smem_u32(Bl + brow * CBPF + bcol));
                    #pragma unroll
                    for (int s2 = 0; s2 < 2; s2++) {
                        const int j = jj * 2 + s2;
                        #pragma unroll
                        for (int rf = 0; rf < 2; rf++) {
                            mma16816(d[rf][j], ah[rf], bh + s2 * 2);
                            mma16816(d[rf][j], al[rf], bh + s2 * 2);
                            mma16816(d[rf][j], ah[rf], bl + s2 * 2);
                        }
                    }
                }
            }

            if ((g & 3) == 3) {
                // register epilogue: v_new[row, r] = sum_p D[row, p] * v[row, p]
                const int nb = g >> 2;
                const int r_loc = nb * 4 + wx;
                float* vcur = v_s[cur];
                float* vnxt = v_s[cur ^ 1];
                #pragma unroll
                for (int rf = 0; rf < 2; rf++) {
                    const int row0 = wy * 32 + rf * 16 + (lane >> 2);
                    float p0 = 0.f, p1 = 0.f;
                    #pragma unroll
                    for (int j = 0; j < 8; j++) {
                        const int p = j * 8 + (lane & 3) * 2;
                        float2 va = *(float2*)&vcur[row0 * 72 + p];
                        float2 vb = *(float2*)&vcur[(row0 + 8) * 72 + p];
                        p0 += d[rf][j][0] * va.x + d[rf][j][1] * va.y;
                        p1 += d[rf][j][2] * vb.x + d[rf][j][3] * vb.y;
                        d[rf][j][0] = 0.f; d[rf][j][1] = 0.f;
                        d[rf][j][2] = 0.f; d[rf][j][3] = 0.f;
                    }
                    p0 += __shfl_xor_sync(0xffffffffu, p0, 1);
                    p0 += __shfl_xor_sync(0xffffffffu, p0, 2);
                    p1 += __shfl_xor_sync(0xffffffffu, p1, 1);
                    p1 += __shfl_xor_sync(0xffffffffu, p1, 2);
                    if ((lane & 3) == 0) {
                        vnxt[row0 * 72 + r_loc] = p0;
                        vnxt[(row0 + 8) * 72 + r_loc] = p1;
                    }
                }
            }
        }
        cur ^= 1;
    }

    // ======== final: out[b] = sum_p v[b,p] * (sum_e enc11[b,e] * Hl[p,e]) ========
    __syncthreads();           // pipeline fully drained; B region free
    for (int i = tid; i < ENCD * Rr; i += 256) {
        int e = i >> 6, p = i & 63;
        scr1[i] = Hl[p * ENCD + e];                 // transposed [e*64+p]
    }
    {
        const bf16* Eh = g_ench + (size_t)(Tn - 1) * Bsz * ENCD;
        const bf16* El = g_encl + (size_t)(Tn - 1) * Bsz * ENCD;
        for (int i = tid; i < 64 * ENCD; i += 256) {
            int r = i >> 7, e = i & 127;
            size_t a = (size_t)(b0 + r) * ENCD + e;
            scr2[r * 128 + e] = __bfloat162float(Eh[a]) + __bfloat162float(El[a]);
        }
    }
    __syncthreads();
    {
        float* red = scr1 + 8192 + 8192;            // 256 floats, still inside B region
        const int row = tid >> 2, q = tid & 3;
        float partial = 0.f;
        #pragma unroll
        for (int pp = 0; pp < 16; pp++) {
            int p = q * 16 + pp;
            float last = 0.f;
            #pragma unroll 8
            for (int e = 0; e < ENCD; e++) last += scr2[row * 128 + e] * scr1[e * 64 + p];
            partial += v_s[cur][row * 72 + p] * last;
        }
        red[row * 4 + q] = partial;
        __syncthreads();
        if (tid < 64)
            out[b0 + tid] = red[tid * 4 + 0] + red[tid * 4 + 1]
                          + red[tid * 4 + 2] + red[tid * 4 + 3];
    }
}

// ================= host launcher =================
extern "C" void kernel_launch(void* const* d_in, const int* in_sizes, int n_in,
                              void* d_out, int out_size) {
    const float* x  = (const float*)d_in[0];
    const float* W1 = (const float*)d_in[1];
    const float* b1 = (const float*)d_in[2];
    const float* W2 = (const float*)d_in[3];
    const float* b2 = (const float*)d_in[4];
    const float* Hf = (const float*)d_in[5];
    const float* Hm = (const float*)d_in[6];
    const float* Hl = (const float*)d_in[7];
    float* out = (float*)d_out;

    cudaFuncSetAttribute(encoder2_kernel,  cudaFuncAttributeMaxDynamicSharedMemorySize, ENC2_SMEM);
    cudaFuncSetAttribute(chain_mma_kernel, cudaFuncAttributeMaxDynamicSharedMemorySize, CHF_SMEM);

    prep_w_kernel<<<96, 256>>>(W1, W2);
    prep_hb_kernel<<<(Tn - 2) * ENCD, 256>>>(Hm);
    encoder2_kernel<<<(Bsz * Tn) / 64, 256, ENC2_SMEM>>>(x, b1, b2);
    chain_mma_kernel<<<128, 256, CHF_SMEM>>>(Hf, Hl, out);
}